// round 9
// baseline (speedup 1.0000x reference)
#include <cuda_runtime.h>
#include <math_constants.h>
#include <cub/block/block_radix_sort.cuh>

#define NCLS    1000
#define NPAD    1024
#define KTOP    5
#define BMAX    64
#define THREADS 1024
#define NWARP   32

__device__ float        g_row_loss[BMAX];
__device__ unsigned int g_done_cnt = 0;

typedef cub::BlockRadixSort<unsigned, THREADS, 1> BlockSort;

// order-preserving float->uint key (monotone); 0 sorts below any valid key
__device__ __forceinline__ unsigned fkey(float f) {
    unsigned b = __float_as_uint(f);
    return (b & 0x80000000u) ? ~b : (b | 0x80000000u);
}
__device__ __forceinline__ float fdec(unsigned k) {
    unsigned b = (k & 0x80000000u) ? (k & 0x7FFFFFFFu) : ~k;
    return __uint_as_float(b);
}

__global__ __launch_bounds__(THREADS)
void topk_fused_kernel(const float* __restrict__ outp,
                       const int*   __restrict__ target,
                       float*       __restrict__ out,
                       int B)
{
    __shared__ typename BlockSort::TempStorage sort_tmp;
    __shared__ float    cs1s[NPAD];      // inclusive prefix sums: cs1s[i] = cs[i+1]
    __shared__ unsigned sol[NPAD];       // per-j max keys
    __shared__ float    rcp[NPAD + 2];   // 1/len table, idx 1..1024
    __shared__ float    wsum[NWARP];
    __shared__ float    red[NWARP];
    __shared__ int      s_p;
    __shared__ int      s_last;

    const int tid = threadIdx.x;
    const int w   = tid >> 5;
    const int l   = tid & 31;
    const int b   = blockIdx.x;
    const float* row = outp + (size_t)b * NCLS;
    const int   tgt = target[b];
    const float vt  = __ldg(row + tgt);  // == s[p] (exact, by p-counting)

    // ---- init + load ----
    if (tid == 0) s_p = 0;
    sol[tid]     = 0u;
    rcp[tid + 1] = 1.0f / (float)(tid + 1);

    float v = (tid < NCLS) ? row[tid] : -CUDART_INF_F;
    unsigned keys[1];
    keys[0] = fkey(v);

    // p = #(v > vt) + #(v == vt && i < tgt)   (stable argsort of -theta)
    bool before = (tid < NCLS) && ((v > vt) || (v == vt && tid < tgt));
    int cnt = __popc(__ballot_sync(0xFFFFFFFFu, before));
    __syncthreads();                     // s_p=0 / sol / rcp visible
    if (l == 0) atomicAdd(&s_p, cnt);

    // ---- sort descending on top 16 bits only (4 radix passes).
    //      Full 32-bit keys move, so the value multiset is exact; only
    //      ordering within 16-bit tie-buckets is approximate (error << 1e-3).
    BlockSort(sort_tmp).SortDescending(keys, 16, 32);
    // CUB's internal barriers also drain the s_p atomics.

    const float sv = fdec(keys[0]);      // sorted value at position tid

    // ---- y = s - w ; inclusive scan (warp shfl + warp-sum scan) ----
    float y = (tid < NCLS) ? sv - (float)(NCLS - tid) : 0.0f;
    float s = y;
    #pragma unroll
    for (int o = 1; o < 32; o <<= 1) {
        float t = __shfl_up_sync(0xFFFFFFFFu, s, o);
        if (l >= o) s += t;
    }
    if (l == 31) wsum[w] = s;
    __syncthreads();
    if (w == 0) {
        float t = wsum[l];
        #pragma unroll
        for (int o = 1; o < 32; o <<= 1) {
            float u = __shfl_up_sync(0xFFFFFFFFu, t, o);
            if (l >= o) t += u;
        }
        wsum[l] = t;
    }
    __syncthreads();
    cs1s[tid] = s + ((w == 0) ? 0.0f : wsum[w - 1]);
    __syncthreads();

    // ---- balanced min-max: sol_p = min_{j<=p} max_{k>=p} (cs[k+1]-cs[j])*rcp[k-j+1]
    //      warps partition the k-range, lanes stride j, merge via atomicMax ----
    const int p  = s_p;
    const int nk = NCLS - p;
    const int kb = p + (nk * w) / NWARP;
    const int ke = p + (nk * (w + 1)) / NWARP;

    if (kb < ke) {
        for (int j = l; j <= p; j += 32) {
            float csj = (j == 0) ? 0.0f : cs1s[j - 1];
            const float* rj = rcp + (1 - j);
            float m0 = -CUDART_INF_F, m1 = -CUDART_INF_F;
            int k = kb;
            for (; k + 1 < ke; k += 2) {
                m0 = fmaxf(m0, (cs1s[k]     - csj) * rj[k]);
                m1 = fmaxf(m1, (cs1s[k + 1] - csj) * rj[k + 1]);
            }
            if (k < ke)
                m0 = fmaxf(m0, (cs1s[k] - csj) * rj[k]);
            atomicMax(&sol[j], fkey(fmaxf(m0, m1)));
        }
    }
    __syncthreads();

    // ---- min over j, block reduce ----
    float gmin = (tid <= p) ? fdec(sol[tid]) : CUDART_INF_F;
    #pragma unroll
    for (int o = 16; o; o >>= 1)
        gmin = fminf(gmin, __shfl_xor_sync(0xFFFFFFFFu, gmin, o));
    if (l == 0) red[w] = gmin;
    __syncthreads();
    if (tid == 0) {
        float m = CUDART_INF_F;
        #pragma unroll
        for (int i = 0; i < NWARP; i++) m = fminf(m, red[i]);
        float rank = vt - m;             // s[p] - sol_p
        g_row_loss[b] = fmaxf(0.0f, (float)(NCLS - KTOP + 1) - rank);
        __threadfence();
        unsigned t = atomicAdd(&g_done_cnt, 1u);
        s_last = (t == (unsigned)(B - 1));
    }
    __syncthreads();

    // ---- last CTA to finish reduces row losses and writes the mean ----
    if (s_last && tid < 32) {
        __threadfence();
        float r = 0.0f;
        for (int i = tid; i < B; i += 32)
            r += g_row_loss[i];
        #pragma unroll
        for (int o = 16; o; o >>= 1)
            r += __shfl_xor_sync(0xFFFFFFFFu, r, o);
        if (tid == 0) {
            out[0] = r / (float)B;
            g_done_cnt = 0;              // reset for next graph replay
            __threadfence();
        }
    }
}

extern "C" void kernel_launch(void* const* d_in, const int* in_sizes, int n_in,
                              void* d_out, int out_size)
{
    const float* outp   = (const float*)d_in[0];
    const int*   target = (const int*)d_in[1];
    float*       out    = (float*)d_out;

    int B = in_sizes[1];
    if (B > BMAX) B = BMAX;

    topk_fused_kernel<<<B, THREADS>>>(outp, target, out, B);
}

// round 11
// speedup vs baseline: 1.0880x; 1.0880x over previous
#include <cuda_runtime.h>
#include <math_constants.h>

#define NCLS    1000
#define KTOP    5
#define BMAX    64
#define THREADS 1024
#define NWARP   32
#define NBKT    2048
#define FPSCALE 1048576.0f   // 2^20 fixed point

__device__ float        g_row_loss[BMAX];
__device__ unsigned int g_done_cnt = 0;

// order-preserving float->uint key; 0 sorts below any valid key
__device__ __forceinline__ unsigned fkey(float f) {
    unsigned b = __float_as_uint(f);
    return (b & 0x80000000u) ? ~b : (b | 0x80000000u);
}
__device__ __forceinline__ float fdec(unsigned k) {
    unsigned b = (k & 0x80000000u) ? (k & 0x7FFFFFFFu) : ~k;
    return __uint_as_float(b);
}

__global__ __launch_bounds__(THREADS)
void topk_fused_kernel(const float* __restrict__ outp,
                       const int*   __restrict__ target,
                       float*       __restrict__ out,
                       int B)
{
    __shared__ int                hcnt[NBKT];     // raw bucket counts
    __shared__ unsigned long long hsum[NBKT];     // fixed-point bucket sums
    __shared__ int                cntI[NBKT];     // inclusive count prefix
    __shared__ float              sumE[NBKT];     // exclusive sum prefix (decoded)
    __shared__ float              bmean[NBKT];    // per-bucket mean value
    __shared__ float              cs1s[THREADS];  // cs1s[k] = cs[k+1]
    __shared__ unsigned           sol[THREADS];   // per-j max keys
    __shared__ float              rcp[THREADS + 2];
    __shared__ int                wcI[NWARP];
    __shared__ long long          wsS[NWARP];
    __shared__ float              red[NWARP];
    __shared__ int                s_p;
    __shared__ int                s_last;

    const int tid = threadIdx.x;
    const int w   = tid >> 5;
    const int l   = tid & 31;
    const int b   = blockIdx.x;
    const float* row = outp + (size_t)b * NCLS;
    const int   tgt = target[b];
    const float vt  = __ldg(row + tgt);   // == s[p] exactly

    // ---- init shared ----
    if (tid == 0) s_p = 0;
    sol[tid]     = 0u;
    rcp[tid + 1] = 1.0f / (float)(tid + 1);
    hcnt[2 * tid]     = 0;  hcnt[2 * tid + 1]     = 0;
    hsum[2 * tid]     = 0ull; hsum[2 * tid + 1]   = 0ull;

    const float v   = (tid < NCLS) ? row[tid] : 0.0f;
    const bool  act = (tid < NCLS);

    // p = #(v > vt) + #(v == vt && i < tgt)  (stable argsort of -theta)
    bool before = act && ((v > vt) || (v == vt && tid < tgt));
    int cnt = __popc(__ballot_sync(0xFFFFFFFFu, before));
    __syncthreads();                                       // (1) init visible
    if (l == 0) atomicAdd(&s_p, cnt);

    // ---- histogram (descending buckets) ----
    if (act) {
        int ia  = (int)floorf((v + 8.0f) * 128.0f);
        ia      = min(max(ia, 0), NBKT - 1);
        int bkt = (NBKT - 1) - ia;
        long long q = llrintf(v * FPSCALE);
        atomicAdd(&hcnt[bkt], 1);
        atomicAdd(&hsum[bkt], (unsigned long long)q);
    }
    __syncthreads();                                       // (2) hist complete

    // ---- joint scan of (cnt, sum) over 2048 buckets; thread owns 2 ----
    {
        int       c0 = hcnt[2 * tid], c1 = hcnt[2 * tid + 1];
        long long q0 = (long long)hsum[2 * tid];
        long long q1 = (long long)hsum[2 * tid + 1];

        int       pc = c0 + c1;
        long long ps = q0 + q1;
        #pragma unroll
        for (int o = 1; o < 32; o <<= 1) {
            int       tc = __shfl_up_sync(0xFFFFFFFFu, pc, o);
            long long ts = __shfl_up_sync(0xFFFFFFFFu, ps, o);
            if (l >= o) { pc += tc; ps += ts; }
        }
        if (l == 31) { wcI[w] = pc; wsS[w] = ps; }
        __syncthreads();                                   // (3)
        if (w == 0) {
            int       tc = wcI[l];
            long long ts = wsS[l];
            #pragma unroll
            for (int o = 1; o < 32; o <<= 1) {
                int       uc = __shfl_up_sync(0xFFFFFFFFu, tc, o);
                long long us = __shfl_up_sync(0xFFFFFFFFu, ts, o);
                if (l >= o) { tc += uc; ts += us; }
            }
            wcI[l] = tc; wsS[l] = ts;
        }
        __syncthreads();                                   // (4)
        int       offC = (w == 0) ? 0   : wcI[w - 1];
        long long offS = (w == 0) ? 0ll : wsS[w - 1];

        int       inclC1 = offC + pc;          // count through bucket 2t+1
        long long inclS1 = offS + ps;
        int       inclC0 = inclC1 - c1;
        long long inclS0 = inclS1 - q1;

        cntI[2 * tid]     = inclC0;
        cntI[2 * tid + 1] = inclC1;
        sumE[2 * tid]     = (float)(inclS0 - q0) * (1.0f / FPSCALE);
        sumE[2 * tid + 1] = (float)inclS0        * (1.0f / FPSCALE);
        bmean[2 * tid]     = c0 ? ((float)q0 * (1.0f / FPSCALE)) / (float)c0 : 0.0f;
        bmean[2 * tid + 1] = c1 ? ((float)q1 * (1.0f / FPSCALE)) / (float)c1 : 0.0f;
    }
    __syncthreads();                                       // (5) prefixes ready

    // ---- cs1s[k] via bucket lookup (binary search, no barrier) ----
    if (act) {
        int k = tid;
        int lo = 0, hi = NBKT - 1;
        #pragma unroll
        for (int it = 0; it < 11; it++) {
            int mid = (lo + hi) >> 1;
            if (cntI[mid] > k) hi = mid; else lo = mid + 1;
        }
        int bkt     = lo;
        int exclC   = cntI[bkt] - hcnt[bkt];
        float sumTh = sumE[bkt] + (float)(k - exclC + 1) * bmean[bkt];
        int   wk    = (k + 1) * NCLS - (k * (k + 1)) / 2;  // sum of w over 0..k
        cs1s[k] = sumTh - (float)wk;
    } else {
        cs1s[tid] = 0.0f;
    }
    __syncthreads();                                       // (6) cs1s ready

    // ---- balanced min-max: sol_p = min_{j<=p} max_{k>=p} (cs[k+1]-cs[j])*rcp[k-j+1]
    const int p  = s_p;
    const int nk = NCLS - p;
    const int kb = p + (nk * w) / NWARP;
    const int ke = p + (nk * (w + 1)) / NWARP;

    if (kb < ke) {
        for (int j = l; j <= p; j += 32) {
            float csj = (j == 0) ? 0.0f : cs1s[j - 1];
            const float* rj = rcp + (1 - j);
            float m0 = -CUDART_INF_F, m1 = -CUDART_INF_F;
            int k = kb;
            for (; k + 1 < ke; k += 2) {
                m0 = fmaxf(m0, (cs1s[k]     - csj) * rj[k]);
                m1 = fmaxf(m1, (cs1s[k + 1] - csj) * rj[k + 1]);
            }
            if (k < ke)
                m0 = fmaxf(m0, (cs1s[k] - csj) * rj[k]);
            atomicMax(&sol[j], fkey(fmaxf(m0, m1)));
        }
    }
    __syncthreads();                                       // (7)

    // ---- min over j, block reduce ----
    float gmin = (tid <= p) ? fdec(sol[tid]) : CUDART_INF_F;
    #pragma unroll
    for (int o = 16; o; o >>= 1)
        gmin = fminf(gmin, __shfl_xor_sync(0xFFFFFFFFu, gmin, o));
    if (l == 0) red[w] = gmin;
    __syncthreads();                                       // (8)
    if (tid == 0) {
        float m = CUDART_INF_F;
        #pragma unroll
        for (int i = 0; i < NWARP; i++) m = fminf(m, red[i]);
        float rank = vt - m;
        g_row_loss[b] = fmaxf(0.0f, (float)(NCLS - KTOP + 1) - rank);
        __threadfence();
        unsigned t = atomicAdd(&g_done_cnt, 1u);
        s_last = (t == (unsigned)(B - 1));
    }
    __syncthreads();                                       // (9)

    // ---- last CTA reduces row losses, writes the mean ----
    if (s_last && tid < 32) {
        __threadfence();
        float r = 0.0f;
        for (int i = tid; i < B; i += 32)
            r += g_row_loss[i];
        #pragma unroll
        for (int o = 16; o; o >>= 1)
            r += __shfl_xor_sync(0xFFFFFFFFu, r, o);
        if (tid == 0) {
            out[0] = r / (float)B;
            g_done_cnt = 0;            // reset for next graph replay
            __threadfence();
        }
    }
}

extern "C" void kernel_launch(void* const* d_in, const int* in_sizes, int n_in,
                              void* d_out, int out_size)
{
    const float* outp   = (const float*)d_in[0];
    const int*   target = (const int*)d_in[1];
    float*       out    = (float*)d_out;

    int B = in_sizes[1];
    if (B > BMAX) B = BMAX;

    topk_fused_kernel<<<B, THREADS>>>(outp, target, out, B);
}

// round 12
// speedup vs baseline: 1.9775x; 1.8175x over previous
#include <cuda_runtime.h>
#include <math_constants.h>

#define NCLS    1000
#define KTOP    5
#define BMAX    64
#define THREADS 1024
#define NWARP   32
#define NBKT    2048
#define FPSCALE 1048576.0f   // 2^20 fixed point
#define MAXROUND 8

__device__ float        g_row_loss[BMAX];
__device__ unsigned int g_done_cnt = 0;

// order-preserving float->uint key; 0 sorts below any valid key
__device__ __forceinline__ unsigned fkey(float f) {
    unsigned b = __float_as_uint(f);
    return (b & 0x80000000u) ? ~b : (b | 0x80000000u);
}
__device__ __forceinline__ float fdec(unsigned k) {
    unsigned b = (k & 0x80000000u) ? (k & 0x7FFFFFFFu) : ~k;
    return __uint_as_float(b);
}

// block-wide max of 64-bit keys; scratch must have 33 slots
__device__ __forceinline__ unsigned long long
blk_max64(unsigned long long v, int w, int l, unsigned long long* scratch)
{
    #pragma unroll
    for (int o = 16; o; o >>= 1) {
        unsigned long long u = __shfl_xor_sync(0xFFFFFFFFu, v, o);
        v = (u > v) ? u : v;
    }
    if (l == 0) scratch[w] = v;
    __syncthreads();
    if (w == 0) {
        unsigned long long t = scratch[l];
        #pragma unroll
        for (int o = 16; o; o >>= 1) {
            unsigned long long u = __shfl_xor_sync(0xFFFFFFFFu, t, o);
            t = (u > t) ? u : t;
        }
        if (l == 0) scratch[32] = t;
    }
    __syncthreads();
    return scratch[32];
}

__global__ __launch_bounds__(THREADS)
void topk_fused_kernel(const float* __restrict__ outp,
                       const int*   __restrict__ target,
                       float*       __restrict__ out,
                       int B)
{
    __shared__ int                hcnt[NBKT];
    __shared__ unsigned long long hsum[NBKT];
    __shared__ int                cntI[NBKT];
    __shared__ float              sumE[NBKT];
    __shared__ float              bmean[NBKT];
    __shared__ float              cs1s[THREADS];   // cs1s[k] = cs[k+1]
    __shared__ unsigned           sol[THREADS];    // fallback only
    __shared__ float              rcp[THREADS + 2];
    __shared__ unsigned long long wred[33];
    __shared__ int                wcI[NWARP];
    __shared__ long long          wsS[NWARP];
    __shared__ float              red[NWARP];
    __shared__ int                s_p;
    __shared__ int                s_last;

    const int tid = threadIdx.x;
    const int w   = tid >> 5;
    const int l   = tid & 31;
    const int b   = blockIdx.x;
    const float* row = outp + (size_t)b * NCLS;
    const int   tgt = target[b];
    const float vt  = __ldg(row + tgt);   // == s[p] exactly

    // ---- init shared ----
    if (tid == 0) s_p = 0;
    rcp[tid + 1] = 1.0f / (float)(tid + 1);
    hcnt[2 * tid]   = 0;    hcnt[2 * tid + 1]   = 0;
    hsum[2 * tid]   = 0ull; hsum[2 * tid + 1]   = 0ull;

    const float v   = (tid < NCLS) ? row[tid] : 0.0f;
    const bool  act = (tid < NCLS);

    // p = #(v > vt) + #(v == vt && i < tgt)
    bool before = act && ((v > vt) || (v == vt && tid < tgt));
    int cnt = __popc(__ballot_sync(0xFFFFFFFFu, before));
    __syncthreads();
    if (l == 0) atomicAdd(&s_p, cnt);

    // ---- histogram (descending buckets) ----
    if (act) {
        int ia  = (int)floorf((v + 8.0f) * 128.0f);
        ia      = min(max(ia, 0), NBKT - 1);
        int bkt = (NBKT - 1) - ia;
        long long q = llrintf(v * FPSCALE);
        atomicAdd(&hcnt[bkt], 1);
        atomicAdd(&hsum[bkt], (unsigned long long)q);
    }
    __syncthreads();

    // ---- joint (count, sum) scan over 2048 buckets; thread owns 2 ----
    {
        int       c0 = hcnt[2 * tid], c1 = hcnt[2 * tid + 1];
        long long q0 = (long long)hsum[2 * tid];
        long long q1 = (long long)hsum[2 * tid + 1];

        int       pc = c0 + c1;
        long long ps = q0 + q1;
        #pragma unroll
        for (int o = 1; o < 32; o <<= 1) {
            int       tc = __shfl_up_sync(0xFFFFFFFFu, pc, o);
            long long ts = __shfl_up_sync(0xFFFFFFFFu, ps, o);
            if (l >= o) { pc += tc; ps += ts; }
        }
        if (l == 31) { wcI[w] = pc; wsS[w] = ps; }
        __syncthreads();
        if (w == 0) {
            int       tc = wcI[l];
            long long ts = wsS[l];
            #pragma unroll
            for (int o = 1; o < 32; o <<= 1) {
                int       uc = __shfl_up_sync(0xFFFFFFFFu, tc, o);
                long long us = __shfl_up_sync(0xFFFFFFFFu, ts, o);
                if (l >= o) { tc += uc; ts += us; }
            }
            wcI[l] = tc; wsS[l] = ts;
        }
        __syncthreads();
        int       offC = (w == 0) ? 0   : wcI[w - 1];
        long long offS = (w == 0) ? 0ll : wsS[w - 1];

        int       inclC1 = offC + pc;
        long long inclS1 = offS + ps;
        int       inclC0 = inclC1 - c1;
        long long inclS0 = inclS1 - q1;

        cntI[2 * tid]     = inclC0;
        cntI[2 * tid + 1] = inclC1;
        sumE[2 * tid]     = (float)(inclS0 - q0) * (1.0f / FPSCALE);
        sumE[2 * tid + 1] = (float)inclS0        * (1.0f / FPSCALE);
        bmean[2 * tid]     = c0 ? ((float)q0 * (1.0f / FPSCALE)) / (float)c0 : 0.0f;
        bmean[2 * tid + 1] = c1 ? ((float)q1 * (1.0f / FPSCALE)) / (float)c1 : 0.0f;
    }
    __syncthreads();

    // ---- cs1s[k] via bucket binary search ----
    if (act) {
        int k = tid;
        int lo = 0, hi = NBKT - 1;
        #pragma unroll
        for (int it = 0; it < 11; it++) {
            int mid = (lo + hi) >> 1;
            if (cntI[mid] > k) hi = mid; else lo = mid + 1;
        }
        int bkt     = lo;
        int exclC   = cntI[bkt] - hcnt[bkt];
        float sumTh = sumE[bkt] + (float)(k - exclC + 1) * bmean[bkt];
        int   wk    = (k + 1) * NCLS - (k * (k + 1)) / 2;
        cs1s[k] = sumTh - (float)wk;
    } else {
        cs1s[tid] = 0.0f;
    }
    __syncthreads();

    const int p = s_p;

    // ---- saddle alternation:
    //   kn = argmax_{k>=p} mean(j..k); jn = argmin_{j<=p} mean(j..kn)
    //   if jn == j, the pair is a saddle: value == min_j max_k exactly. ----
    float solp = 0.0f;
    bool  conv = false;
    int   jj   = p;
    for (int round = 0; round < MAXROUND; round++) {
        float csj = (jj == 0) ? 0.0f : cs1s[jj - 1];
        unsigned long long key = 0ull;
        if (tid >= p && tid < NCLS) {
            float m = (cs1s[tid] - csj) * rcp[tid - jj + 1];
            key = ((unsigned long long)fkey(m) << 32) | (unsigned)(2048 - tid);
        }
        key = blk_max64(key, w, l, wred);
        const int   kn = 2048 - (int)(key & 0xFFFFFFFFull);
        const float mk = fdec((unsigned)(key >> 32));

        const float csk = cs1s[kn];
        unsigned long long key2 = 0ull;
        if (tid <= p) {
            float c  = (tid == 0) ? 0.0f : cs1s[tid - 1];
            float m2 = (csk - c) * rcp[kn - tid + 1];
            key2 = ((unsigned long long)fkey(-m2) << 32) | (unsigned)(2048 - tid);
        }
        key2 = blk_max64(key2, w, l, wred);
        const int jn = 2048 - (int)(key2 & 0xFFFFFFFFull);

        if (jn == jj) { conv = true; solp = mk; break; }
        jj = jn;
    }

    // ---- exact fallback (rarely taken): full rectangle min-max ----
    if (!conv) {
        sol[tid] = 0u;
        __syncthreads();
        const int nk = NCLS - p;
        const int kb = p + (nk * w) / NWARP;
        const int ke = p + (nk * (w + 1)) / NWARP;
        if (kb < ke) {
            for (int j = l; j <= p; j += 32) {
                float csj = (j == 0) ? 0.0f : cs1s[j - 1];
                const float* rj = rcp + (1 - j);
                float m0 = -CUDART_INF_F, m1 = -CUDART_INF_F;
                int k = kb;
                for (; k + 1 < ke; k += 2) {
                    m0 = fmaxf(m0, (cs1s[k]     - csj) * rj[k]);
                    m1 = fmaxf(m1, (cs1s[k + 1] - csj) * rj[k + 1]);
                }
                if (k < ke)
                    m0 = fmaxf(m0, (cs1s[k] - csj) * rj[k]);
                atomicMax(&sol[j], fkey(fmaxf(m0, m1)));
            }
        }
        __syncthreads();
        float gmin = (tid <= p) ? fdec(sol[tid]) : CUDART_INF_F;
        #pragma unroll
        for (int o = 16; o; o >>= 1)
            gmin = fminf(gmin, __shfl_xor_sync(0xFFFFFFFFu, gmin, o));
        if (l == 0) red[w] = gmin;
        __syncthreads();
        if (tid == 0) {
            float m = CUDART_INF_F;
            #pragma unroll
            for (int i = 0; i < NWARP; i++) m = fminf(m, red[i]);
            red[0] = m;
        }
        __syncthreads();
        solp = red[0];
    }

    // ---- loss + cross-CTA completion ----
    if (tid == 0) {
        float rank = vt - solp;
        g_row_loss[b] = fmaxf(0.0f, (float)(NCLS - KTOP + 1) - rank);
        __threadfence();
        unsigned t = atomicAdd(&g_done_cnt, 1u);
        s_last = (t == (unsigned)(B - 1));
    }
    __syncthreads();

    if (s_last && tid < 32) {
        __threadfence();
        float r = 0.0f;
        for (int i = tid; i < B; i += 32)
            r += g_row_loss[i];
        #pragma unroll
        for (int o = 16; o; o >>= 1)
            r += __shfl_xor_sync(0xFFFFFFFFu, r, o);
        if (tid == 0) {
            out[0] = r / (float)B;
            g_done_cnt = 0;              // reset for next graph replay
            __threadfence();
        }
    }
}

extern "C" void kernel_launch(void* const* d_in, const int* in_sizes, int n_in,
                              void* d_out, int out_size)
{
    const float* outp   = (const float*)d_in[0];
    const int*   target = (const int*)d_in[1];
    float*       out    = (float*)d_out;

    int B = in_sizes[1];
    if (B > BMAX) B = BMAX;

    topk_fused_kernel<<<B, THREADS>>>(outp, target, out, B);
}